// round 1
// baseline (speedup 1.0000x reference)
#include <cuda_runtime.h>

#define N_NODES 10000
#define N_EDGES 320000
#define HID 64
#define NPAD 10112            // 79 * 128
#define NB 79

// ---------------- static device scratch (no allocation allowed) ----------------
__device__ int   g_is64;
__device__ int   d_src[N_EDGES];
__device__ int   d_dst[N_EDGES];
__device__ float d_hA[N_NODES * HID];
__device__ float d_hB[N_NODES * HID];
__device__ float d_agg[N_NODES * HID];
__device__ float d_g[N_NODES * HID];
__device__ float d_Gt[HID * NPAD];
__device__ float d_Ht[HID * NPAD];
__device__ float d_rowm[N_NODES];
__device__ float d_rowinv[N_NODES];
__device__ float d_L[(size_t)N_NODES * N_NODES];   // 400 MB logits scratch

// ---------------- edge_index width detection ----------------
// int64 little-endian node ids < 10000 => every odd 32-bit word is 0.
__global__ void detect_kernel(const unsigned int* __restrict__ raw) {
    unsigned acc = 0;
    for (int i = threadIdx.x; i < 4096; i += 32) acc |= raw[2 * i + 1];
#pragma unroll
    for (int o = 16; o; o >>= 1) acc |= __shfl_xor_sync(0xffffffffu, acc, o);
    if (threadIdx.x == 0) g_is64 = (acc == 0) ? 1 : 0;
}

__global__ void convert_kernel(const unsigned int* __restrict__ raw) {
    int e = blockIdx.x * blockDim.x + threadIdx.x;
    if (e >= N_EDGES) return;
    if (g_is64) {
        d_src[e] = (int)raw[2 * e];
        d_dst[e] = (int)raw[2 * (N_EDGES + e)];
    } else {
        d_src[e] = (int)raw[e];
        d_dst[e] = (int)raw[N_EDGES + e];
    }
}

// ---------------- h0 = x @ W_in + b_in ----------------
__global__ void node_embed_kernel(const float* __restrict__ x,
                                  const float* __restrict__ Win,
                                  const float* __restrict__ bin) {
    int n = blockIdx.x, h = threadIdx.x;
    __shared__ float xs[24];
    if (h < 24) xs[h] = x[n * 24 + h];
    __syncthreads();
    float a = bin[h];
#pragma unroll
    for (int k = 0; k < 24; k++) a = fmaf(xs[k], Win[k * HID + h], a);
    d_hA[n * HID + h] = a;
}

__global__ void zero_agg_kernel() {
    int i = blockIdx.x * 256 + threadIdx.x;
    if (i < N_NODES * HID) d_agg[i] = 0.f;
}

// ---------------- message + scatter-add: agg[dst] += relu(h[src] + ea) ----------------
// ea recomputed on the fly from edge_attr (2 floats) -> saves 3x82MB of traffic.
__global__ void edge_kernel(const float* __restrict__ eattr,
                            const float* __restrict__ We,
                            const float* __restrict__ be, int sel) {
    int idx = blockIdx.x * 256 + threadIdx.x;
    if (idx >= N_EDGES * 16) return;
    int e = idx >> 4;
    int c = (idx & 15) * 4;
    const float* hin = sel ? d_hB : d_hA;
    int s = d_src[e], d = d_dst[e];
    float2 a  = *(const float2*)(eattr + 2 * e);
    float4 h4 = *(const float4*)(hin + s * HID + c);
    float4 w0 = *(const float4*)(We + c);
    float4 w1 = *(const float4*)(We + HID + c);
    float4 b4 = *(const float4*)(be + c);
    float v0 = fmaxf(h4.x + fmaf(a.x, w0.x, fmaf(a.y, w1.x, b4.x)), 0.f);
    float v1 = fmaxf(h4.y + fmaf(a.x, w0.y, fmaf(a.y, w1.y, b4.y)), 0.f);
    float v2 = fmaxf(h4.z + fmaf(a.x, w0.z, fmaf(a.y, w1.z, b4.z)), 0.f);
    float v3 = fmaxf(h4.w + fmaf(a.x, w0.w, fmaf(a.y, w1.w, b4.w)), 0.f);
    asm volatile("red.global.add.v4.f32 [%0], {%1,%2,%3,%4};"
                 :: "l"(d_agg + d * HID + c),
                    "f"(v0), "f"(v1), "f"(v2), "f"(v3) : "memory");
}

// ---------------- shared MLP: out = [relu](relu((h+agg)@W1+b1)@W2+b2) ----------------
__global__ void mlp_kernel(const float* __restrict__ W1, const float* __restrict__ b1,
                           const float* __restrict__ W2, const float* __restrict__ b2,
                           int sel, int do_relu) {
    int n = blockIdx.x, h = threadIdx.x;
    const float* hin  = sel ? d_hB : d_hA;
    float*       hout = sel ? d_hA : d_hB;
    __shared__ float zs[HID];
    __shared__ float ts[HID];
    zs[h] = hin[n * HID + h] + d_agg[n * HID + h];
    __syncthreads();
    float t = b1[h];
#pragma unroll 16
    for (int k = 0; k < HID; k++) t = fmaf(zs[k], W1[k * HID + h], t);
    ts[h] = fmaxf(t, 0.f);
    __syncthreads();
    float o = b2[h];
#pragma unroll 16
    for (int k = 0; k < HID; k++) o = fmaf(ts[k], W2[k * HID + h], o);
    hout[n * HID + h] = do_relu ? fmaxf(o, 0.f) : o;
}

// ---------------- g = h @ M ----------------
__global__ void gmat_kernel(const float* __restrict__ M) {
    int n = blockIdx.x, h = threadIdx.x;
    __shared__ float hs[HID];
    hs[h] = d_hA[n * HID + h];
    __syncthreads();
    float o = 0.f;
#pragma unroll 16
    for (int k = 0; k < HID; k++) o = fmaf(hs[k], M[k * HID + h], o);
    d_g[n * HID + h] = o;
}

// ---------------- transpose to [K][NPAD] (zero-padded) for coalesced GEMM loads ----------------
__global__ void transpose_kernel(int which) {
    int idx = blockIdx.x * 256 + threadIdx.x;
    if (idx >= HID * NPAD) return;
    int k = idx / NPAD, j = idx - k * NPAD;
    const float* src = which ? d_hA : d_g;
    float*       dst = which ? d_Ht : d_Gt;
    dst[idx] = (j < N_NODES) ? src[j * HID + k] : 0.f;
}

// ---------------- L = g @ h^T : 128x128 tiles, 8x8 per thread, K=64 resident ----------------
__global__ void __launch_bounds__(256) gemm_kernel() {
    __shared__ float Gs[HID][128];
    __shared__ float Hs[HID][128];
    int i0 = blockIdx.y * 128, j0 = blockIdx.x * 128;
    int tid = threadIdx.x;
    for (int t = tid; t < HID * 32; t += 256) {
        int k = t >> 5, c = (t & 31) * 4;
        *(float4*)&Gs[k][c] = *(const float4*)&d_Gt[k * NPAD + i0 + c];
        *(float4*)&Hs[k][c] = *(const float4*)&d_Ht[k * NPAD + j0 + c];
    }
    __syncthreads();
    int tx = tid & 15, ty = tid >> 4;
    float acc[8][8];
#pragma unroll
    for (int i = 0; i < 8; i++)
#pragma unroll
        for (int j = 0; j < 8; j++) acc[i][j] = 0.f;

#pragma unroll 8
    for (int k = 0; k < HID; k++) {
        float a[8], b[8];
        *(float4*)&a[0] = *(float4*)&Gs[k][ty * 8];
        *(float4*)&a[4] = *(float4*)&Gs[k][ty * 8 + 4];
        *(float4*)&b[0] = *(float4*)&Hs[k][tx * 8];
        *(float4*)&b[4] = *(float4*)&Hs[k][tx * 8 + 4];
#pragma unroll
        for (int i = 0; i < 8; i++)
#pragma unroll
            for (int j = 0; j < 8; j++) acc[i][j] = fmaf(a[i], b[j], acc[i][j]);
    }

    int ib = i0 + ty * 8, jb = j0 + tx * 8;
#pragma unroll
    for (int i = 0; i < 8; i++) {
        int gi = ib + i;
        if (gi < N_NODES) {
            float* dst = d_L + (size_t)gi * N_NODES + jb;
            if (jb + 8 <= N_NODES) {
                *(float4*)dst       = make_float4(acc[i][0], acc[i][1], acc[i][2], acc[i][3]);
                *(float4*)(dst + 4) = make_float4(acc[i][4], acc[i][5], acc[i][6], acc[i][7]);
            } else {
#pragma unroll
                for (int j = 0; j < 8; j++)
                    if (jb + j < N_NODES) dst[j] = acc[i][j];
            }
        }
    }
}

// ---------------- per-row online softmax stats (single read of L) ----------------
__global__ void rowstat_kernel() {
    int i = blockIdx.x;
    int tid = threadIdx.x;
    const float4* row = (const float4*)(d_L + (size_t)i * N_NODES);
    float m = -3.4e38f, s = 0.f;
    for (int j = tid; j < N_NODES / 4; j += 256) {
        float4 v = row[j];
        float lm = fmaxf(fmaxf(v.x, v.y), fmaxf(v.z, v.w));
        if (lm > m) { s *= __expf(m - lm); m = lm; }
        s += __expf(v.x - m) + __expf(v.y - m) + __expf(v.z - m) + __expf(v.w - m);
    }
    __shared__ float sm[256], ss[256];
    sm[tid] = m; ss[tid] = s;
    __syncthreads();
    for (int off = 128; off; off >>= 1) {
        if (tid < off) {
            float m2 = sm[tid + off], s2 = ss[tid + off];
            float mm = fmaxf(sm[tid], m2);
            ss[tid] = ss[tid] * __expf(sm[tid] - mm) + s2 * __expf(m2 - mm);
            sm[tid] = mm;
        }
        __syncthreads();
    }
    if (tid == 0) { d_rowm[i] = sm[0]; d_rowinv[i] = 1.f / ss[0]; }
}

// ---------------- out = exp(L - m) * inv ----------------
__global__ void finalize_kernel(float* __restrict__ out) {
    int i  = blockIdx.y;
    int j4 = blockIdx.x * 256 + threadIdx.x;
    if (j4 >= N_NODES / 4) return;
    float m = d_rowm[i], inv = d_rowinv[i];
    size_t idx = (size_t)i * (N_NODES / 4) + j4;
    float4 v = ((const float4*)d_L)[idx];
    float4 o;
    o.x = __expf(v.x - m) * inv;
    o.y = __expf(v.y - m) * inv;
    o.z = __expf(v.z - m) * inv;
    o.w = __expf(v.w - m) * inv;
    ((float4*)out)[idx] = o;
}

extern "C" void kernel_launch(void* const* d_in, const int* in_sizes, int n_in,
                              void* d_out, int out_size) {
    const float*    x     = (const float*)d_in[0];
    const float*    eattr = (const float*)d_in[1];
    const unsigned* eidx  = (const unsigned*)d_in[2];
    const float*    Win   = (const float*)d_in[3];
    const float*    bin   = (const float*)d_in[4];
    const float*    We    = (const float*)d_in[5];
    const float*    be    = (const float*)d_in[6];
    const float*    W1    = (const float*)d_in[7];
    const float*    b1    = (const float*)d_in[8];
    const float*    W2    = (const float*)d_in[9];
    const float*    b2    = (const float*)d_in[10];
    const float*    M     = (const float*)d_in[11];
    float*          out   = (float*)d_out;

    detect_kernel<<<1, 32>>>(eidx);
    convert_kernel<<<(N_EDGES + 255) / 256, 256>>>(eidx);

    node_embed_kernel<<<N_NODES, HID>>>(x, Win, bin);

    // GINE layer 1: read hA -> write hB (relu on output)
    zero_agg_kernel<<<(N_NODES * HID + 255) / 256, 256>>>();
    edge_kernel<<<(N_EDGES * 16 + 255) / 256, 256>>>(eattr, We, be, 0);
    mlp_kernel<<<N_NODES, HID>>>(W1, b1, W2, b2, 0, 1);

    // GINE layer 2: read hB -> write hA (no relu)
    zero_agg_kernel<<<(N_NODES * HID + 255) / 256, 256>>>();
    edge_kernel<<<(N_EDGES * 16 + 255) / 256, 256>>>(eattr, We, be, 1);
    mlp_kernel<<<N_NODES, HID>>>(W1, b1, W2, b2, 1, 0);

    // decode
    gmat_kernel<<<N_NODES, HID>>>(M);
    transpose_kernel<<<(HID * NPAD + 255) / 256, 256>>>(0);  // g  -> Gt
    transpose_kernel<<<(HID * NPAD + 255) / 256, 256>>>(1);  // hA -> Ht

    dim3 ggrid(NB, NB);
    gemm_kernel<<<ggrid, 256>>>();

    rowstat_kernel<<<N_NODES, 256>>>();

    dim3 fgrid((N_NODES / 4 + 255) / 256, N_NODES);
    finalize_kernel<<<fgrid, 256>>>(out);
}